// round 10
// baseline (speedup 1.0000x reference)
#include <cuda_runtime.h>
#include <cstdint>

// Embedding gather with L2-locality binning.
// weight: [1'000'000, 128] f32 (512 MB), index: [2'097'152] i32, out: 1 GB.
//
// Phase 1: bin indices by weight region. NB=32 buckets of 2^15 rows = 16 MB
//          of table each; the ~2-slice resident window (32 MB) stays fully
//          L2-resident next to the streaming writes, so repeat rows hit.
// Phase 2: ONE gather kernel; blocks mapped to buckets contiguously
//          (bucket = bid >> 10) so resident blocks share one slice.
// Cursor reset is fused into the gather tail with a fence-free acq_rel
// done-counter (R8's __threadfence emitted CCTL.IVALL = per-block L1D flush,
// which is what killed that attempt). No separate zero kernel.

static constexpr int NB       = 32;
static constexpr int BSHIFT   = 15;               // 2^15 rows per bucket
static constexpr int CAP      = 96 * 1024;        // >> max bucket count (~66K)
static constexpr int C        = 16;               // 32 B chunks per 512 B row
static constexpr int IT       = 8;                // items per thread in scatter
static constexpr int BPB_LOG2 = 10;               // 1024 gather blocks per bucket

__device__ int2 g_bins[NB][CAP];                  // (pos, idx), 24 MB scratch
__device__ int  g_cursor[NB];                     // zero-init; restored each run
__device__ int  g_done;                           // zero-init; restored each run

__global__ __launch_bounds__(256) void scatter_kernel(
    const int4* __restrict__ index4, int n_index)
{
    __shared__ int sh_cnt[NB];
    __shared__ int sh_base[NB];

    if (threadIdx.x < NB) sh_cnt[threadIdx.x] = 0;
    __syncthreads();

    // IT=8 indices per thread via two int4 loads. n_index is a multiple of
    // 2048, so every int4 load is in-bounds when tbase < n_index.
    const long long tbase = ((long long)blockIdx.x * blockDim.x + threadIdx.x) * IT;

    int idx[IT], bkt[IT], rank[IT];
    bool active = (tbase < n_index);
    if (active) {
        int4 a = __ldg(&index4[tbase / 4]);
        int4 b = __ldg(&index4[tbase / 4 + 1]);
        idx[0] = a.x; idx[1] = a.y; idx[2] = a.z; idx[3] = a.w;
        idx[4] = b.x; idx[5] = b.y; idx[6] = b.z; idx[7] = b.w;
#pragma unroll
        for (int i = 0; i < IT; i++) {
            bkt[i]  = idx[i] >> BSHIFT;
            rank[i] = atomicAdd(&sh_cnt[bkt[i]], 1);
        }
    }
    __syncthreads();

    if (threadIdx.x < NB)
        sh_base[threadIdx.x] = atomicAdd(&g_cursor[threadIdx.x], sh_cnt[threadIdx.x]);
    __syncthreads();

    if (active) {
#pragma unroll
        for (int i = 0; i < IT; i++) {
            int slot = sh_base[bkt[i]] + rank[i];
            if (slot < CAP)                       // statistically impossible guard
                g_bins[bkt[i]][slot] = make_int2((int)(tbase + i), idx[i]);
        }
    }
}

__device__ __forceinline__ ulonglong4 ldg256_evict_last(const ulonglong4* p) {
    ulonglong4 v;
    asm volatile("ld.global.nc.L2::evict_last.v4.u64 {%0,%1,%2,%3}, [%4];"
                 : "=l"(v.x), "=l"(v.y), "=l"(v.z), "=l"(v.w)
                 : "l"(p));
    return v;
}

__device__ __forceinline__ void stg256_cs(ulonglong4* p, const ulonglong4& v) {
    asm volatile("st.global.cs.v4.u64 [%0], {%1,%2,%3,%4};"
                 :: "l"(p), "l"(v.x), "l"(v.y), "l"(v.z), "l"(v.w)
                 : "memory");
}

// Fused gather: bucket = bid >> BPB_LOG2. Within a bucket, 1024 blocks
// grid-stride over the bucket's entries. Warp handles 8 entries as 4
// (even,odd) pairs; a half-warp moves one 512 B row with 256-bit ld/st.
// Last finishing block resets the cursors (fence-free).
__global__ __launch_bounds__(256) void gather_all_kernel(
    const ulonglong4* __restrict__ weight,
    ulonglong4*       __restrict__ out)
{
    const int bucket    = blockIdx.x >> BPB_LOG2;
    const int local_bid = blockIdx.x & ((1 << BPB_LOG2) - 1);

    int cnt = g_cursor[bucket];
    if (cnt > CAP) cnt = CAP;

    const int lane = threadIdx.x & 31;
    const int sub  = lane >> 4;                   // 0: even entry, 1: odd entry
    const int l16  = lane & 15;

    const int warps_per_bucket = (1 << BPB_LOG2) * (256 / 32);
    const int warp_id = local_bid * 8 + (threadIdx.x >> 5);
    const long long stride = (long long)warps_per_bucket * 8;

    const int2* bin = g_bins[bucket];

    for (long long base = (long long)warp_id * 8; base < cnt; base += stride) {
        int2 ent[4];
#pragma unroll
        for (int p = 0; p < 4; p++) {
            long long e = base + 2 * p + sub;
            ent[p] = (e < cnt) ? __ldg(&bin[e]) : make_int2(0, 0);
        }

        ulonglong4 v[4];
#pragma unroll
        for (int p = 0; p < 4; p++)
            v[p] = ldg256_evict_last(&weight[(size_t)ent[p].y * C + l16]);

#pragma unroll
        for (int p = 0; p < 4; p++) {
            long long e = base + 2 * p + sub;
            if (e < cnt)
                stg256_cs(&out[(size_t)ent[p].x * C + l16], v[p]);
        }
    }

    // Fence-free fused reset. __syncthreads ensures every thread of this
    // block has consumed its g_cursor read; the acq_rel RMW orders the
    // resetter's writes after all blocks' reads (no CCTL.IVALL / L1D flush,
    // unlike __threadfence). Kernel-boundary ordering publishes the zeros to
    // the next replay's scatter.
    __syncthreads();
    if (threadIdx.x == 0) {
        int d;
        asm volatile("atom.acq_rel.gpu.global.add.s32 %0, [%1], %2;"
                     : "=r"(d) : "l"(&g_done), "r"(1) : "memory");
        if (d == (int)gridDim.x - 1) {
#pragma unroll
            for (int i = 0; i < NB; i++) g_cursor[i] = 0;
            g_done = 0;
        }
    }
}

extern "C" void kernel_launch(void* const* d_in, const int* in_sizes, int n_in,
                              void* d_out, int out_size)
{
    const ulonglong4* weight = (const ulonglong4*)d_in[0];
    const int*        index  = (const int*)d_in[1];
    ulonglong4*       out    = (ulonglong4*)d_out;

    const int n_index = in_sizes[1];              // 2,097,152

    const int sthreads = 256;
    const long long per_block = (long long)sthreads * IT;   // 2048
    const int sblocks = (int)((n_index + per_block - 1) / per_block);
    scatter_kernel<<<sblocks, sthreads>>>((const int4*)index, n_index);

    // 1024 blocks per bucket x 32 buckets = 32768 blocks, one launch.
    gather_all_kernel<<<NB << BPB_LOG2, 256>>>(weight, out);
}

// round 11
// speedup vs baseline: 1.0315x; 1.0315x over previous
#include <cuda_runtime.h>
#include <cstdint>

// Embedding gather, single-kernel filter-and-gather.
// weight: [1'000'000, 128] f32 (512 MB), index: [2'097'152] i32, out: 1 GB.
//
// NB=32 L2 slices of the table (16 MB each). grid = 32 buckets x 1024 blocks;
// blocks are bucket-contiguous so resident blocks share one slice in L2 and
// repeat rows (~57% of draws) hit in L2 (DRAM reads ~450 MB, not 1045 MB).
//
// No scatter/bins: the 8 MB index is L2-resident, so each block re-reads its
// 2048-entry index slice (32x total read amplification, all L2 hits) and
// filters for its bucket (~64 matches), compacting (pos, idx) pairs into
// shared memory. This removes the separate scatter kernel, its launch gap,
// 34 MB of bin traffic, and all global state (stateless -> nothing to reset).

static constexpr int NB       = 32;
static constexpr int BSHIFT   = 15;               // 2^15 rows per bucket
static constexpr int BPB_LOG2 = 10;               // 1024 blocks per bucket
static constexpr int BPB      = 1 << BPB_LOG2;
static constexpr int IPB      = 2048;             // index slice per block
static constexpr int C        = 16;               // 32 B chunks per 512 B row
static constexpr int LCAP     = 256;              // shared list capacity

__device__ __forceinline__ ulonglong4 ldg256_evict_last(const ulonglong4* p) {
    ulonglong4 v;
    asm volatile("ld.global.nc.L2::evict_last.v4.u64 {%0,%1,%2,%3}, [%4];"
                 : "=l"(v.x), "=l"(v.y), "=l"(v.z), "=l"(v.w)
                 : "l"(p));
    return v;
}

__device__ __forceinline__ void stg256_cs(ulonglong4* p, const ulonglong4& v) {
    asm volatile("st.global.cs.v4.u64 [%0], {%1,%2,%3,%4};"
                 :: "l"(p), "l"(v.x), "l"(v.y), "l"(v.z), "l"(v.w)
                 : "memory");
}

__global__ __launch_bounds__(256) void gather_kernel(
    const ulonglong4* __restrict__ weight,
    const int4*       __restrict__ index4,
    ulonglong4*       __restrict__ out,
    int n_index)
{
    __shared__ int2 list[LCAP];
    __shared__ int  count;

    const int bucket = blockIdx.x >> BPB_LOG2;
    const int lbid   = blockIdx.x & (BPB - 1);
    const int tid    = threadIdx.x;

    if (tid == 0) count = 0;
    __syncthreads();

    // ---- Filter phase: scan this block's 2048-index slice (L2-resident). ----
    // 8 indices per thread via two int4 loads. n_index is a multiple of 2048,
    // so when the slice start is in-bounds both loads are in-bounds.
    const long long tpos = (long long)lbid * IPB + tid * 8;
    if (tpos < n_index) {
        int4 a = __ldg(&index4[tpos / 4]);
        int4 b = __ldg(&index4[tpos / 4 + 1]);
        int idx[8] = {a.x, a.y, a.z, a.w, b.x, b.y, b.z, b.w};
#pragma unroll
        for (int i = 0; i < 8; i++) {
            if ((idx[i] >> BSHIFT) == bucket) {
                int slot = atomicAdd(&count, 1);
                if (slot < LCAP) {
                    list[slot] = make_int2((int)(tpos + i), idx[i]);
                } else {
                    // Statistically unreachable (mean 64, cap 256) but must be
                    // correct: this thread copies the row itself, 16 x 32 B.
                    const ulonglong4* src = &weight[(size_t)idx[i] * C];
                    ulonglong4*       dst = &out[(tpos + i) * C];
#pragma unroll
                    for (int c = 0; c < C; c++)
                        stg256_cs(&dst[c], ldg256_evict_last(&src[c]));
                }
            }
        }
    }
    __syncthreads();

    int cnt = count;
    if (cnt > LCAP) cnt = LCAP;

    // ---- Gather phase: proven half-warp / 256-bit pattern. ----
    // Warp handles 8 entries as 4 (even,odd) pairs; a half-warp (16 lanes x
    // 32 B) moves one 512 B row. 8 warps x 8 entries = 64 per pass (~= mean).
    const int lane = tid & 31;
    const int sub  = lane >> 4;                   // 0: even entry, 1: odd entry
    const int l16  = lane & 15;
    const int warp = tid >> 5;

    for (int base = warp * 8; base < cnt; base += 8 * 8) {
        int2 ent[4];
#pragma unroll
        for (int p = 0; p < 4; p++) {
            int e = base + 2 * p + sub;
            ent[p] = (e < cnt) ? list[e] : make_int2(0, 0);
        }

        ulonglong4 v[4];
#pragma unroll
        for (int p = 0; p < 4; p++)
            v[p] = ldg256_evict_last(&weight[(size_t)ent[p].y * C + l16]);

#pragma unroll
        for (int p = 0; p < 4; p++) {
            int e = base + 2 * p + sub;
            if (e < cnt)
                stg256_cs(&out[(size_t)ent[p].x * C + l16], v[p]);
        }
    }
}

extern "C" void kernel_launch(void* const* d_in, const int* in_sizes, int n_in,
                              void* d_out, int out_size)
{
    const ulonglong4* weight = (const ulonglong4*)d_in[0];
    const int4*       index4 = (const int4*)d_in[1];
    ulonglong4*       out    = (ulonglong4*)d_out;

    const int n_index = in_sizes[1];              // 2,097,152 = 1024 * 2048

    // One launch: 32 buckets x 1024 blocks.
    gather_kernel<<<NB << BPB_LOG2, 256>>>(weight, index4, out, n_index);
}

// round 12
// speedup vs baseline: 1.0353x; 1.0037x over previous
#include <cuda_runtime.h>
#include <cstdint>

// Embedding gather, single-kernel filter-and-gather.
// weight: [1'000'000, 128] f32 (512 MB), index: [2'097'152] i32, out: 1 GB.
//
// NB=32 L2 slices of the table (16 MB each). grid = 32 buckets x 1024 blocks;
// blocks are bucket-contiguous so resident blocks share one slice in L2 and
// repeat rows (~57% of draws) hit in L2 (DRAM reads ~450 MB, not 1045 MB).
//
// No scatter/bins: the 8 MB index is L2-resident; each block re-reads its
// 2048-entry index slice, filters for its bucket (~64 matches), compacts
// (pos, idx) pairs into shared memory, then gathers with half-warp 256-bit
// ld/st. R12: gather pass narrowed to 2 row-pairs (v[2] = 16 regs instead of
// 32) and the overflow fallback is __noinline__ -- per-warp MLP was ~4x what
// latency hiding needs, and the saved registers lift occupancy 50% -> ~80%.

static constexpr int NB       = 32;
static constexpr int BSHIFT   = 15;               // 2^15 rows per bucket
static constexpr int BPB_LOG2 = 10;               // 1024 blocks per bucket
static constexpr int BPB      = 1 << BPB_LOG2;
static constexpr int IPB      = 2048;             // index slice per block
static constexpr int C        = 16;               // 32 B chunks per 512 B row
static constexpr int LCAP     = 256;              // shared list capacity

__device__ __forceinline__ ulonglong4 ldg256_evict_last(const ulonglong4* p) {
    ulonglong4 v;
    asm volatile("ld.global.nc.L2::evict_last.v4.u64 {%0,%1,%2,%3}, [%4];"
                 : "=l"(v.x), "=l"(v.y), "=l"(v.z), "=l"(v.w)
                 : "l"(p));
    return v;
}

__device__ __forceinline__ void stg256_cs(ulonglong4* p, const ulonglong4& v) {
    asm volatile("st.global.cs.v4.u64 [%0], {%1,%2,%3,%4};"
                 :: "l"(p), "l"(v.x), "l"(v.y), "l"(v.z), "l"(v.w)
                 : "memory");
}

// Statistically unreachable (list cap 256 vs mean 64); kept correct but out
// of the hot path's register budget.
__device__ __noinline__ void overflow_copy_row(
    const ulonglong4* __restrict__ weight,
    ulonglong4*       __restrict__ out,
    int idx, long long pos)
{
    const ulonglong4* src = &weight[(size_t)idx * C];
    ulonglong4*       dst = &out[pos * C];
#pragma unroll
    for (int c = 0; c < C; c++)
        stg256_cs(&dst[c], ldg256_evict_last(&src[c]));
}

__global__ __launch_bounds__(256) void gather_kernel(
    const ulonglong4* __restrict__ weight,
    const int4*       __restrict__ index4,
    ulonglong4*       __restrict__ out,
    int n_index)
{
    __shared__ int2 list[LCAP];
    __shared__ int  count;

    const int bucket = blockIdx.x >> BPB_LOG2;
    const int lbid   = blockIdx.x & (BPB - 1);
    const int tid    = threadIdx.x;

    if (tid == 0) count = 0;
    __syncthreads();

    // ---- Filter phase: scan this block's 2048-index slice (L2-resident). ----
    const long long tpos = (long long)lbid * IPB + tid * 8;
    if (tpos < n_index) {
        int4 a = __ldg(&index4[tpos / 4]);
        int4 b = __ldg(&index4[tpos / 4 + 1]);
        int idx[8] = {a.x, a.y, a.z, a.w, b.x, b.y, b.z, b.w};
#pragma unroll
        for (int i = 0; i < 8; i++) {
            if ((idx[i] >> BSHIFT) == bucket) {
                int slot = atomicAdd(&count, 1);
                if (slot < LCAP)
                    list[slot] = make_int2((int)(tpos + i), idx[i]);
                else
                    overflow_copy_row(weight, out, idx[i], tpos + i);
            }
        }
    }
    __syncthreads();

    int cnt = count;
    if (cnt > LCAP) cnt = LCAP;

    // ---- Gather phase: half-warp / 256-bit pattern, 2 pairs per pass. ----
    // Warp handles 4 entries as 2 (even,odd) pairs; a half-warp (16 lanes x
    // 32 B) moves one 512 B row. 8 warps x 4 entries = 32 per pass.
    const int lane = tid & 31;
    const int sub  = lane >> 4;                   // 0: even entry, 1: odd entry
    const int l16  = lane & 15;
    const int warp = tid >> 5;

    for (int base = warp * 4; base < cnt; base += 8 * 4) {
        int2 ent[2];
#pragma unroll
        for (int p = 0; p < 2; p++) {
            int e = base + 2 * p + sub;
            ent[p] = (e < cnt) ? list[e] : make_int2(0, 0);
        }

        ulonglong4 v[2];
#pragma unroll
        for (int p = 0; p < 2; p++)
            v[p] = ldg256_evict_last(&weight[(size_t)ent[p].y * C + l16]);

#pragma unroll
        for (int p = 0; p < 2; p++) {
            int e = base + 2 * p + sub;
            if (e < cnt)
                stg256_cs(&out[(size_t)ent[p].x * C + l16], v[p]);
        }
    }
}

extern "C" void kernel_launch(void* const* d_in, const int* in_sizes, int n_in,
                              void* d_out, int out_size)
{
    const ulonglong4* weight = (const ulonglong4*)d_in[0];
    const int4*       index4 = (const int4*)d_in[1];
    ulonglong4*       out    = (ulonglong4*)d_out;

    const int n_index = in_sizes[1];              // 2,097,152 = 1024 * 2048

    gather_kernel<<<NB << BPB_LOG2, 256>>>(weight, index4, out, n_index);
}